// round 10
// baseline (speedup 1.0000x reference)
#include <cuda_runtime.h>
#include <math.h>
#include <stdint.h>

typedef unsigned long long ull;

#define Bv 2
#define Nv 10000
#define Ev 160000
#define Hv 128
#define ETv 8
#define BN (Bv*Nv)          // 20000
#define EPSv 1e-5f
#define RSQRT_H 0.08838834764831843f

// ---------------- scratch ----------------
__device__ float g_Q[BN*Hv];
__device__ float g_K[BN*Hv];
__device__ float g_V[BN*Hv];
__device__ float g_Agg[BN*Hv];
__device__ float g_Hmid[BN*Hv];
__device__ float g_segsum[BN];
__device__ float g_Ke[ETv*Hv];
__device__ float g_Ve[ETv*Hv];
__device__ float g_eL[ETv];

// ---------------- helpers ----------------
__device__ __forceinline__ void red_add_v4(float* p, float4 v) {
    asm volatile("red.global.add.v4.f32 [%0], {%1,%2,%3,%4};"
                 :: "l"(p), "f"(v.x), "f"(v.y), "f"(v.z), "f"(v.w) : "memory");
}
// packed f32x2 fma: d += a * b  (per 32-bit lane)
__device__ __forceinline__ void fma2(ull& d, ull a, ull b) {
    asm("fma.rn.f32x2 %0, %1, %2, %0;" : "+l"(d) : "l"(a), "l"(b));
}
__device__ __forceinline__ ull dup2(float v) {
    ull r; unsigned u = __float_as_uint(v);
    asm("mov.b64 %0, {%1, %1};" : "=l"(r) : "r"(u));
    return r;
}
__device__ __forceinline__ void unpack2(ull v, float& lo, float& hi) {
    unsigned a, b;
    asm("mov.b64 {%0, %1}, %2;" : "=r"(a), "=r"(b) : "l"(v));
    lo = __uint_as_float(a); hi = __uint_as_float(b);
}

// ---------------- 0: zero scratch ----------------
__global__ void zero_init() {
    int i = blockIdx.x * blockDim.x + threadIdx.x;
    int stride = gridDim.x * blockDim.x;
    for (int j = i; j < BN*Hv; j += stride) g_Agg[j] = 0.0f;
    for (int j = i; j < BN; j += stride) g_segsum[j] = 0.0f;
}

// ---------------- 1: edge-type projections (tiny) ----------------
__global__ void prep_edge(const float* __restrict__ eemb,
                          const float* __restrict__ Wk,
                          const float* __restrict__ Wv,
                          const float* __restrict__ We,
                          const float* __restrict__ be) {
    int t = threadIdx.x >> 7;
    int j = threadIdx.x & 127;
    float ake = 0.f, ave = 0.f;
    #pragma unroll 4
    for (int k = 0; k < Hv; k++) {
        float e = eemb[t*Hv + k];
        ake += e * Wk[k*Hv + j];
        ave += e * Wv[k*Hv + j];
    }
    g_Ke[t*Hv + j] = ake;
    g_Ve[t*Hv + j] = ave;
    if (j == 0) {
        float s = 0.f;
        for (int k = 0; k < Hv; k++) s += eemb[t*Hv + k] * We[k];
        g_eL[t] = s + be[0];
    }
}

// ================= R2-style f32x2 GEMM framework =================
// Tile: 64 rows x 128 cols, 128 threads, 8x8 per thread.
#define TM 64
#define KC 32
#define APAD 36

__device__ __forceinline__ void mm_chunk(const float* As, const float* Ws,
                                         int r0, int c0,
                                         ull acc[8][4]) {
    #pragma unroll
    for (int k = 0; k < KC; k++) {
        ulonglong2 b0 = *(const ulonglong2*)&Ws[k*Hv + c0];
        ulonglong2 b1 = *(const ulonglong2*)&Ws[k*Hv + c0 + 4];
        #pragma unroll
        for (int r = 0; r < 8; r++) {
            ull aa = dup2(As[(r0 + r)*APAD + k]);
            fma2(acc[r][0], aa, b0.x);
            fma2(acc[r][1], aa, b0.y);
            fma2(acc[r][2], aa, b1.x);
            fma2(acc[r][3], aa, b1.y);
        }
    }
}

__device__ __forceinline__ void load_w(const float* __restrict__ W, int k0,
                                       float* Ws, int tid) {
    #pragma unroll
    for (int i = 0; i < 8; i++) {
        int lin = tid + i*128;
        int wr = lin >> 5; int wc = (lin & 31) * 4;
        *(float4*)&Ws[wr*Hv + wc] = *(const float4*)&W[(k0 + wr)*Hv + wc];
    }
}

// ---------------- 2: QKV GEMM (z selects Q/K/V) ----------------
__global__ void __launch_bounds__(128)
gemm_qkv(const float* __restrict__ hidden, const float* __restrict__ temb,
         const float* __restrict__ Wq, const float* __restrict__ bq,
         const float* __restrict__ Wk, const float* __restrict__ bk,
         const float* __restrict__ Wv, const float* __restrict__ bv)
{
    int which = blockIdx.z;
    const float* W    = which == 0 ? Wq : (which == 1 ? Wk : Wv);
    const float* bias = which == 0 ? bq : (which == 1 ? bk : bv);
    float* out        = which == 0 ? g_Q : (which == 1 ? g_K : g_V);
    bool addT = (which < 2);

    __shared__ float As[TM*APAD];
    __shared__ float Ws[KC*Hv];
    int tid = threadIdx.x;
    int rg = tid >> 4, cg = tid & 15;
    int r0 = rg * 8, c0 = cg * 8;
    int row0 = blockIdx.x * TM;

    ull acc[8][4];
    #pragma unroll
    for (int r = 0; r < 8; r++)
        #pragma unroll
        for (int c = 0; c < 4; c++) acc[r][c] = 0ull;

    for (int k0 = 0; k0 < Hv; k0 += KC) {
        #pragma unroll
        for (int i = 0; i < 4; i++) {
            int lin = tid + i*128;
            int r = lin >> 3; int kk = (lin & 7) * 4;
            int row = row0 + r;
            float4 a = make_float4(0.f,0.f,0.f,0.f);
            if (row < BN) {
                a = *(const float4*)&hidden[row*Hv + k0 + kk];
                if (addT) {
                    float4 b = *(const float4*)&temb[row*Hv + k0 + kk];
                    a.x += b.x; a.y += b.y; a.z += b.z; a.w += b.w;
                }
            }
            *(float4*)&As[r*APAD + kk] = a;
        }
        load_w(W, k0, Ws, tid);
        __syncthreads();
        mm_chunk(As, Ws, r0, c0, acc);
        __syncthreads();
    }
    float4 bi0 = *(const float4*)&bias[c0];
    float4 bi1 = *(const float4*)&bias[c0 + 4];
    #pragma unroll
    for (int r = 0; r < 8; r++) {
        int row = row0 + r0 + r;
        if (row < BN) {
            float v0,v1,v2,v3,v4,v5,v6,v7;
            unpack2(acc[r][0], v0, v1); unpack2(acc[r][1], v2, v3);
            unpack2(acc[r][2], v4, v5); unpack2(acc[r][3], v6, v7);
            *(float4*)&out[row*Hv + c0] =
                make_float4(v0+bi0.x, v1+bi0.y, v2+bi0.z, v3+bi0.w);
            *(float4*)&out[row*Hv + c0 + 4] =
                make_float4(v4+bi1.x, v5+bi1.y, v6+bi1.z, v7+bi1.w);
        }
    }
}

// ---------------- 3: FUSED edge kernel (no max-shift softmax) ----------------
__global__ void edge_fused(const int* __restrict__ eidx, const int* __restrict__ etype)
{
    int w = (blockIdx.x * blockDim.x + threadIdx.x) >> 5;
    int lane = threadIdx.x & 31;
    if (w >= Ev) return;
    int src = eidx[w];
    int tgt = eidx[Ev + w];
    int ty  = etype[w];
    float4 ke = *(const float4*)&g_Ke[ty*Hv + lane*4];
    float4 ve = *(const float4*)&g_Ve[ty*Hv + lane*4];
    float el = g_eL[ty];

    float4 q0 = *(const float4*)&g_Q[(0*Nv + tgt)*Hv + lane*4];
    float4 k0 = *(const float4*)&g_K[(0*Nv + src)*Hv + lane*4];
    float4 q1 = *(const float4*)&g_Q[(1*Nv + tgt)*Hv + lane*4];
    float4 k1 = *(const float4*)&g_K[(1*Nv + src)*Hv + lane*4];

    float s0 = q0.x*(k0.x+ke.x) + q0.y*(k0.y+ke.y) + q0.z*(k0.z+ke.z) + q0.w*(k0.w+ke.w);
    float s1 = q1.x*(k1.x+ke.x) + q1.y*(k1.y+ke.y) + q1.z*(k1.z+ke.z) + q1.w*(k1.w+ke.w);
    #pragma unroll
    for (int off = 16; off > 0; off >>= 1) {
        s0 += __shfl_xor_sync(0xffffffffu, s0, off);
        s1 += __shfl_xor_sync(0xffffffffu, s1, off);
    }
    float ex0 = expf(s0 * RSQRT_H + el);
    float ex1 = expf(s1 * RSQRT_H + el);
    if (lane == 0) {
        atomicAdd(&g_segsum[tgt], ex0);
        atomicAdd(&g_segsum[Nv + tgt], ex1);
    }
    float4 v0 = *(const float4*)&g_V[(0*Nv + src)*Hv + lane*4];
    float4 v1 = *(const float4*)&g_V[(1*Nv + src)*Hv + lane*4];
    float4 a0 = make_float4(ex0*(v0.x+ve.x), ex0*(v0.y+ve.y),
                            ex0*(v0.z+ve.z), ex0*(v0.w+ve.w));
    float4 a1 = make_float4(ex1*(v1.x+ve.x), ex1*(v1.y+ve.y),
                            ex1*(v1.z+ve.z), ex1*(v1.w+ve.w));
    red_add_v4(&g_Agg[(0*Nv + tgt)*Hv + lane*4], a0);
    red_add_v4(&g_Agg[(1*Nv + tgt)*Hv + lane*4], a1);
}

// ---------------- 4: MLP GEMM1 (Agg normalization fused into A-load) ----------------
__global__ void __launch_bounds__(128)
gemm_mlp1(const float* __restrict__ hidden, const float* __restrict__ temb,
          const float* __restrict__ W1, const float* __restrict__ b1)
{
    __shared__ float As[TM*APAD];
    __shared__ float Ws[KC*Hv];
    int tid = threadIdx.x;
    int rg = tid >> 4, cg = tid & 15;
    int r0 = rg * 8, c0 = cg * 8;
    int row0 = blockIdx.x * TM;

    ull acc[8][4];
    #pragma unroll
    for (int r = 0; r < 8; r++)
        #pragma unroll
        for (int c = 0; c < 4; c++) acc[r][c] = 0ull;

    for (int k0 = 0; k0 < 3*Hv; k0 += KC) {
        int srcsel = k0 >> 7;          // 0: hidden, 1: agg, 2: temb
        int off = k0 & 127;
        const float* S = srcsel == 0 ? hidden : (srcsel == 1 ? g_Agg : temb);
        #pragma unroll
        for (int i = 0; i < 4; i++) {
            int lin = tid + i*128;
            int r = lin >> 3; int kk = (lin & 7) * 4;
            int row = row0 + r;
            float4 a = make_float4(0.f,0.f,0.f,0.f);
            if (row < BN) {
                a = *(const float4*)&S[row*Hv + off + kk];
                if (srcsel == 1) {
                    float s = g_segsum[row];
                    float inv = (s > 0.f) ? 1.f/s : 0.f;
                    a.x *= inv; a.y *= inv; a.z *= inv; a.w *= inv;
                }
            }
            *(float4*)&As[r*APAD + kk] = a;
        }
        load_w(W1, k0, Ws, tid);
        __syncthreads();
        mm_chunk(As, Ws, r0, c0, acc);
        __syncthreads();
    }
    float4 bi0 = *(const float4*)&b1[c0];
    float4 bi1 = *(const float4*)&b1[c0 + 4];
    #pragma unroll
    for (int r = 0; r < 8; r++) {
        int row = row0 + r0 + r;
        if (row < BN) {
            float v[8];
            unpack2(acc[r][0], v[0], v[1]); unpack2(acc[r][1], v[2], v[3]);
            unpack2(acc[r][2], v[4], v[5]); unpack2(acc[r][3], v[6], v[7]);
            v[0]+=bi0.x; v[1]+=bi0.y; v[2]+=bi0.z; v[3]+=bi0.w;
            v[4]+=bi1.x; v[5]+=bi1.y; v[6]+=bi1.z; v[7]+=bi1.w;
            #pragma unroll
            for (int j = 0; j < 8; j++) v[j] = v[j] / (1.f + expf(-v[j]));
            *(float4*)&g_Hmid[row*Hv + c0]     = make_float4(v[0],v[1],v[2],v[3]);
            *(float4*)&g_Hmid[row*Hv + c0 + 4] = make_float4(v[4],v[5],v[6],v[7]);
        }
    }
}

// ---------------- 5: GEMM2 + residual + LayerNorm ----------------
__global__ void __launch_bounds__(128)
gemm2_ln(const float* __restrict__ hidden,
         const float* __restrict__ W2, const float* __restrict__ b2,
         const float* __restrict__ gamma, const float* __restrict__ beta,
         float* __restrict__ out)
{
    __shared__ float As[TM*APAD];
    __shared__ float Ws[KC*Hv];
    int tid = threadIdx.x;
    int rg = tid >> 4, cg = tid & 15;
    int r0 = rg * 8, c0 = cg * 8;
    int row0 = blockIdx.x * TM;

    ull acc[8][4];
    #pragma unroll
    for (int r = 0; r < 8; r++)
        #pragma unroll
        for (int c = 0; c < 4; c++) acc[r][c] = 0ull;

    for (int k0 = 0; k0 < Hv; k0 += KC) {
        #pragma unroll
        for (int i = 0; i < 4; i++) {
            int lin = tid + i*128;
            int r = lin >> 3; int kk = (lin & 7) * 4;
            int row = row0 + r;
            float4 a = make_float4(0.f,0.f,0.f,0.f);
            if (row < BN) a = *(const float4*)&g_Hmid[row*Hv + k0 + kk];
            *(float4*)&As[r*APAD + kk] = a;
        }
        load_w(W2, k0, Ws, tid);
        __syncthreads();
        mm_chunk(As, Ws, r0, c0, acc);
        __syncthreads();
    }

    float4 b20 = *(const float4*)&b2[c0];
    float4 b21 = *(const float4*)&b2[c0 + 4];
    float4 gv0 = *(const float4*)&gamma[c0];
    float4 gv1 = *(const float4*)&gamma[c0 + 4];
    float4 be0 = *(const float4*)&beta[c0];
    float4 be1 = *(const float4*)&beta[c0 + 4];

    #pragma unroll
    for (int r = 0; r < 8; r++) {
        int row = row0 + r0 + r;
        float x[8];
        if (row < BN) {
            float4 h0 = *(const float4*)&hidden[row*Hv + c0];
            float4 h1 = *(const float4*)&hidden[row*Hv + c0 + 4];
            float v[8];
            unpack2(acc[r][0], v[0], v[1]); unpack2(acc[r][1], v[2], v[3]);
            unpack2(acc[r][2], v[4], v[5]); unpack2(acc[r][3], v[6], v[7]);
            x[0] = v[0]+b20.x+h0.x; x[1] = v[1]+b20.y+h0.y;
            x[2] = v[2]+b20.z+h0.z; x[3] = v[3]+b20.w+h0.w;
            x[4] = v[4]+b21.x+h1.x; x[5] = v[5]+b21.y+h1.y;
            x[6] = v[6]+b21.z+h1.z; x[7] = v[7]+b21.w+h1.w;
        } else {
            #pragma unroll
            for (int j = 0; j < 8; j++) x[j] = 0.f;
        }
        float s = 0.f, ss = 0.f;
        #pragma unroll
        for (int j = 0; j < 8; j++) { s += x[j]; ss += x[j]*x[j]; }
        #pragma unroll
        for (int off = 8; off > 0; off >>= 1) {
            s  += __shfl_xor_sync(0xffffffffu, s, off);
            ss += __shfl_xor_sync(0xffffffffu, ss, off);
        }
        if (row < BN) {
            float mean = s * (1.f/128.f);
            float var  = ss * (1.f/128.f) - mean*mean;
            float rstd = rsqrtf(var + EPSv);
            float4 o0, o1;
            o0.x = (x[0]-mean)*rstd*gv0.x + be0.x;
            o0.y = (x[1]-mean)*rstd*gv0.y + be0.y;
            o0.z = (x[2]-mean)*rstd*gv0.z + be0.z;
            o0.w = (x[3]-mean)*rstd*gv0.w + be0.w;
            o1.x = (x[4]-mean)*rstd*gv1.x + be1.x;
            o1.y = (x[5]-mean)*rstd*gv1.y + be1.y;
            o1.z = (x[6]-mean)*rstd*gv1.z + be1.z;
            o1.w = (x[7]-mean)*rstd*gv1.w + be1.w;
            *(float4*)&out[row*Hv + c0]     = o0;
            *(float4*)&out[row*Hv + c0 + 4] = o1;
        }
    }
}

// ---------------- launch ----------------
extern "C" void kernel_launch(void* const* d_in, const int* in_sizes, int n_in,
                              void* d_out, int out_size)
{
    const float* hidden = (const float*)d_in[0];
    const float* temb   = (const float*)d_in[1];
    const int*   eidx   = (const int*)d_in[2];
    const int*   etype  = (const int*)d_in[3];
    const float* eemb   = (const float*)d_in[4];
    const float* Wq = (const float*)d_in[5];  const float* bq = (const float*)d_in[6];
    const float* Wk = (const float*)d_in[7];  const float* bk = (const float*)d_in[8];
    const float* Wv = (const float*)d_in[9];  const float* bv = (const float*)d_in[10];
    const float* We = (const float*)d_in[11]; const float* be = (const float*)d_in[12];
    const float* W1 = (const float*)d_in[13]; const float* b1 = (const float*)d_in[14];
    const float* W2 = (const float*)d_in[15]; const float* b2 = (const float*)d_in[16];
    const float* gamma = (const float*)d_in[17]; const float* beta = (const float*)d_in[18];
    float* out = (float*)d_out;

    int gb = (BN + TM - 1)/TM;   // 313
    zero_init<<<2560, 256>>>();
    prep_edge<<<1, 1024>>>(eemb, Wk, Wv, We, be);
    dim3 gq(gb, 1, 3);
    gemm_qkv<<<gq, 128>>>(hidden, temb, Wq, bq, Wk, bk, Wv, bv);
    edge_fused<<<Ev/8, 256>>>(eidx, etype);
    gemm_mlp1<<<gb, 128>>>(hidden, temb, W1, b1);
    gemm2_ln<<<gb, 128>>>(hidden, W2, b2, gamma, beta, out);
}

// round 11
// speedup vs baseline: 1.5447x; 1.5447x over previous
#include <cuda_runtime.h>
#include <math.h>
#include <stdint.h>

typedef unsigned long long ull;

#define Bv 2
#define Nv 10000
#define Ev 160000
#define Hv 128
#define ETv 8
#define BN (Bv*Nv)          // 20000
#define EPSv 1e-5f
#define RSQRT_H 0.08838834764831843f

// ---------------- scratch ----------------
// Q/K/V/Agg are batch-interleaved: index (node*2 + batch)*Hv
__device__ float g_Q[BN*Hv];
__device__ float g_K[BN*Hv];
__device__ float g_V[BN*Hv];
__device__ float g_Agg[BN*Hv];
__device__ float g_Hmid[BN*Hv];
__device__ float g_segsum[BN];     // node*2 + batch
__device__ float g_Ke[ETv*Hv];
__device__ float g_Ve[ETv*Hv];
__device__ float g_eL[ETv];

// row (b*Nv+node) -> interleaved row (node*2+b)
__device__ __forceinline__ int irow_of(int row) {
    int b = row >= Nv;
    return (row - b*Nv)*2 + b;
}

// ---------------- helpers ----------------
__device__ __forceinline__ void red_add_v4(float* p, float4 v) {
    asm volatile("red.global.add.v4.f32 [%0], {%1,%2,%3,%4};"
                 :: "l"(p), "f"(v.x), "f"(v.y), "f"(v.z), "f"(v.w) : "memory");
}
__device__ __forceinline__ void fma2(ull& d, ull a, ull b) {
    asm("fma.rn.f32x2 %0, %1, %2, %0;" : "+l"(d) : "l"(a), "l"(b));
}
__device__ __forceinline__ ull dup2(float v) {
    ull r; unsigned u = __float_as_uint(v);
    asm("mov.b64 %0, {%1, %1};" : "=l"(r) : "r"(u));
    return r;
}
__device__ __forceinline__ void unpack2(ull v, float& lo, float& hi) {
    unsigned a, b;
    asm("mov.b64 {%0, %1}, %2;" : "=r"(a), "=r"(b) : "l"(v));
    lo = __uint_as_float(a); hi = __uint_as_float(b);
}
__device__ __forceinline__ float4 ldg4(const float* p) {
    return __ldg((const float4*)p);
}

// ---------------- 0: zero scratch ----------------
__global__ void zero_init() {
    int i = blockIdx.x * blockDim.x + threadIdx.x;
    int stride = gridDim.x * blockDim.x;
    for (int j = i; j < BN*Hv; j += stride) g_Agg[j] = 0.0f;
    for (int j = i; j < BN; j += stride) g_segsum[j] = 0.0f;
}

// ---------------- 1: edge-type projections (tiny) ----------------
__global__ void prep_edge(const float* __restrict__ eemb,
                          const float* __restrict__ Wk,
                          const float* __restrict__ Wv,
                          const float* __restrict__ We,
                          const float* __restrict__ be) {
    int t = threadIdx.x >> 7;
    int j = threadIdx.x & 127;
    float ake = 0.f, ave = 0.f;
    #pragma unroll 4
    for (int k = 0; k < Hv; k++) {
        float e = eemb[t*Hv + k];
        ake += e * Wk[k*Hv + j];
        ave += e * Wv[k*Hv + j];
    }
    g_Ke[t*Hv + j] = ake;
    g_Ve[t*Hv + j] = ave;
    if (j == 0) {
        float s = 0.f;
        for (int k = 0; k < Hv; k++) s += eemb[t*Hv + k] * We[k];
        g_eL[t] = s + be[0];
    }
}

// ================= R2-style f32x2 GEMM framework =================
#define TM 64
#define KC 32
#define APAD 36

__device__ __forceinline__ void mm_chunk(const float* As, const float* Ws,
                                         int r0, int c0,
                                         ull acc[8][4]) {
    #pragma unroll
    for (int k = 0; k < KC; k++) {
        ulonglong2 b0 = *(const ulonglong2*)&Ws[k*Hv + c0];
        ulonglong2 b1 = *(const ulonglong2*)&Ws[k*Hv + c0 + 4];
        #pragma unroll
        for (int r = 0; r < 8; r++) {
            ull aa = dup2(As[(r0 + r)*APAD + k]);
            fma2(acc[r][0], aa, b0.x);
            fma2(acc[r][1], aa, b0.y);
            fma2(acc[r][2], aa, b1.x);
            fma2(acc[r][3], aa, b1.y);
        }
    }
}

__device__ __forceinline__ void load_w(const float* __restrict__ W, int k0,
                                       float* Ws, int tid) {
    #pragma unroll
    for (int i = 0; i < 8; i++) {
        int lin = tid + i*128;
        int wr = lin >> 5; int wc = (lin & 31) * 4;
        *(float4*)&Ws[wr*Hv + wc] = *(const float4*)&W[(k0 + wr)*Hv + wc];
    }
}

// ---------------- 2: QKV GEMM (z selects Q/K/V) ----------------
__global__ void __launch_bounds__(128)
gemm_qkv(const float* __restrict__ hidden, const float* __restrict__ temb,
         const float* __restrict__ Wq, const float* __restrict__ bq,
         const float* __restrict__ Wk, const float* __restrict__ bk,
         const float* __restrict__ Wv, const float* __restrict__ bv)
{
    int which = blockIdx.z;
    const float* W    = which == 0 ? Wq : (which == 1 ? Wk : Wv);
    const float* bias = which == 0 ? bq : (which == 1 ? bk : bv);
    float* out        = which == 0 ? g_Q : (which == 1 ? g_K : g_V);
    bool addT = (which < 2);

    __shared__ float As[TM*APAD];
    __shared__ float Ws[KC*Hv];
    int tid = threadIdx.x;
    int rg = tid >> 4, cg = tid & 15;
    int r0 = rg * 8, c0 = cg * 8;
    int row0 = blockIdx.x * TM;

    ull acc[8][4];
    #pragma unroll
    for (int r = 0; r < 8; r++)
        #pragma unroll
        for (int c = 0; c < 4; c++) acc[r][c] = 0ull;

    for (int k0 = 0; k0 < Hv; k0 += KC) {
        #pragma unroll
        for (int i = 0; i < 4; i++) {
            int lin = tid + i*128;
            int r = lin >> 3; int kk = (lin & 7) * 4;
            int row = row0 + r;
            float4 a = make_float4(0.f,0.f,0.f,0.f);
            if (row < BN) {
                a = *(const float4*)&hidden[row*Hv + k0 + kk];
                if (addT) {
                    float4 b = *(const float4*)&temb[row*Hv + k0 + kk];
                    a.x += b.x; a.y += b.y; a.z += b.z; a.w += b.w;
                }
            }
            *(float4*)&As[r*APAD + kk] = a;
        }
        load_w(W, k0, Ws, tid);
        __syncthreads();
        mm_chunk(As, Ws, r0, c0, acc);
        __syncthreads();
    }
    float4 bi0 = *(const float4*)&bias[c0];
    float4 bi1 = *(const float4*)&bias[c0 + 4];
    #pragma unroll
    for (int r = 0; r < 8; r++) {
        int row = row0 + r0 + r;
        if (row < BN) {
            int ir = irow_of(row);
            float v0,v1,v2,v3,v4,v5,v6,v7;
            unpack2(acc[r][0], v0, v1); unpack2(acc[r][1], v2, v3);
            unpack2(acc[r][2], v4, v5); unpack2(acc[r][3], v6, v7);
            *(float4*)&out[ir*Hv + c0] =
                make_float4(v0+bi0.x, v1+bi0.y, v2+bi0.z, v3+bi0.w);
            *(float4*)&out[ir*Hv + c0 + 4] =
                make_float4(v4+bi1.x, v5+bi1.y, v6+bi1.z, v7+bi1.w);
        }
    }
}

// ---------------- 3: FUSED edge kernel (interleaved gathers) ----------------
__global__ void edge_fused(const int* __restrict__ eidx, const int* __restrict__ etype)
{
    int w = (blockIdx.x * blockDim.x + threadIdx.x) >> 5;
    int lane = threadIdx.x & 31;
    if (w >= Ev) return;
    int src = eidx[w];
    int tgt = eidx[Ev + w];
    int ty  = etype[w];
    float4 ke = ldg4(&g_Ke[ty*Hv + lane*4]);
    float4 ve = ldg4(&g_Ve[ty*Hv + lane*4]);
    float el = __ldg(&g_eL[ty]);

    // interleaved: batch0/batch1 rows are adjacent (1KB contiguous per node)
    const float* qb = &g_Q[(tgt*2)*Hv + lane*4];
    const float* kb = &g_K[(src*2)*Hv + lane*4];
    float4 q0 = ldg4(qb);
    float4 k0 = ldg4(kb);
    float4 q1 = ldg4(qb + Hv);
    float4 k1 = ldg4(kb + Hv);

    float s0 = q0.x*(k0.x+ke.x) + q0.y*(k0.y+ke.y) + q0.z*(k0.z+ke.z) + q0.w*(k0.w+ke.w);
    float s1 = q1.x*(k1.x+ke.x) + q1.y*(k1.y+ke.y) + q1.z*(k1.z+ke.z) + q1.w*(k1.w+ke.w);
    #pragma unroll
    for (int off = 16; off > 0; off >>= 1) {
        s0 += __shfl_xor_sync(0xffffffffu, s0, off);
        s1 += __shfl_xor_sync(0xffffffffu, s1, off);
    }
    float ex0 = expf(s0 * RSQRT_H + el);
    float ex1 = expf(s1 * RSQRT_H + el);
    if (lane == 0) {
        atomicAdd(&g_segsum[tgt*2],     ex0);
        atomicAdd(&g_segsum[tgt*2 + 1], ex1);
    }
    const float* vb = &g_V[(src*2)*Hv + lane*4];
    float4 v0 = ldg4(vb);
    float4 v1 = ldg4(vb + Hv);
    float4 a0 = make_float4(ex0*(v0.x+ve.x), ex0*(v0.y+ve.y),
                            ex0*(v0.z+ve.z), ex0*(v0.w+ve.w));
    float4 a1 = make_float4(ex1*(v1.x+ve.x), ex1*(v1.y+ve.y),
                            ex1*(v1.z+ve.z), ex1*(v1.w+ve.w));
    float* ab = &g_Agg[(tgt*2)*Hv + lane*4];
    red_add_v4(ab, a0);
    red_add_v4(ab + Hv, a1);
}

// ---------------- 4: MLP GEMM1 (Agg normalization fused into A-load) ----------------
__global__ void __launch_bounds__(128)
gemm_mlp1(const float* __restrict__ hidden, const float* __restrict__ temb,
          const float* __restrict__ W1, const float* __restrict__ b1)
{
    __shared__ float As[TM*APAD];
    __shared__ float Ws[KC*Hv];
    int tid = threadIdx.x;
    int rg = tid >> 4, cg = tid & 15;
    int r0 = rg * 8, c0 = cg * 8;
    int row0 = blockIdx.x * TM;

    ull acc[8][4];
    #pragma unroll
    for (int r = 0; r < 8; r++)
        #pragma unroll
        for (int c = 0; c < 4; c++) acc[r][c] = 0ull;

    for (int k0 = 0; k0 < 3*Hv; k0 += KC) {
        int srcsel = k0 >> 7;          // 0: hidden, 1: agg, 2: temb
        int off = k0 & 127;
        #pragma unroll
        for (int i = 0; i < 4; i++) {
            int lin = tid + i*128;
            int r = lin >> 3; int kk = (lin & 7) * 4;
            int row = row0 + r;
            float4 a = make_float4(0.f,0.f,0.f,0.f);
            if (row < BN) {
                if (srcsel == 1) {
                    int ir = irow_of(row);
                    a = *(const float4*)&g_Agg[ir*Hv + off + kk];
                    float s = g_segsum[ir];
                    float inv = (s > 0.f) ? 1.f/s : 0.f;
                    a.x *= inv; a.y *= inv; a.z *= inv; a.w *= inv;
                } else {
                    const float* S = (srcsel == 0) ? hidden : temb;
                    a = *(const float4*)&S[row*Hv + off + kk];
                }
            }
            *(float4*)&As[r*APAD + kk] = a;
        }
        load_w(W1, k0, Ws, tid);
        __syncthreads();
        mm_chunk(As, Ws, r0, c0, acc);
        __syncthreads();
    }
    float4 bi0 = *(const float4*)&b1[c0];
    float4 bi1 = *(const float4*)&b1[c0 + 4];
    #pragma unroll
    for (int r = 0; r < 8; r++) {
        int row = row0 + r0 + r;
        if (row < BN) {
            float v[8];
            unpack2(acc[r][0], v[0], v[1]); unpack2(acc[r][1], v[2], v[3]);
            unpack2(acc[r][2], v[4], v[5]); unpack2(acc[r][3], v[6], v[7]);
            v[0]+=bi0.x; v[1]+=bi0.y; v[2]+=bi0.z; v[3]+=bi0.w;
            v[4]+=bi1.x; v[5]+=bi1.y; v[6]+=bi1.z; v[7]+=bi1.w;
            #pragma unroll
            for (int j = 0; j < 8; j++) v[j] = v[j] / (1.f + expf(-v[j]));
            *(float4*)&g_Hmid[row*Hv + c0]     = make_float4(v[0],v[1],v[2],v[3]);
            *(float4*)&g_Hmid[row*Hv + c0 + 4] = make_float4(v[4],v[5],v[6],v[7]);
        }
    }
}

// ---------------- 5: GEMM2 + residual + LayerNorm ----------------
__global__ void __launch_bounds__(128)
gemm2_ln(const float* __restrict__ hidden,
         const float* __restrict__ W2, const float* __restrict__ b2,
         const float* __restrict__ gamma, const float* __restrict__ beta,
         float* __restrict__ out)
{
    __shared__ float As[TM*APAD];
    __shared__ float Ws[KC*Hv];
    int tid = threadIdx.x;
    int rg = tid >> 4, cg = tid & 15;
    int r0 = rg * 8, c0 = cg * 8;
    int row0 = blockIdx.x * TM;

    ull acc[8][4];
    #pragma unroll
    for (int r = 0; r < 8; r++)
        #pragma unroll
        for (int c = 0; c < 4; c++) acc[r][c] = 0ull;

    for (int k0 = 0; k0 < Hv; k0 += KC) {
        #pragma unroll
        for (int i = 0; i < 4; i++) {
            int lin = tid + i*128;
            int r = lin >> 3; int kk = (lin & 7) * 4;
            int row = row0 + r;
            float4 a = make_float4(0.f,0.f,0.f,0.f);
            if (row < BN) a = *(const float4*)&g_Hmid[row*Hv + k0 + kk];
            *(float4*)&As[r*APAD + kk] = a;
        }
        load_w(W2, k0, Ws, tid);
        __syncthreads();
        mm_chunk(As, Ws, r0, c0, acc);
        __syncthreads();
    }

    float4 b20 = *(const float4*)&b2[c0];
    float4 b21 = *(const float4*)&b2[c0 + 4];
    float4 gv0 = *(const float4*)&gamma[c0];
    float4 gv1 = *(const float4*)&gamma[c0 + 4];
    float4 be0 = *(const float4*)&beta[c0];
    float4 be1 = *(const float4*)&beta[c0 + 4];

    #pragma unroll
    for (int r = 0; r < 8; r++) {
        int row = row0 + r0 + r;
        float x[8];
        if (row < BN) {
            float4 h0 = *(const float4*)&hidden[row*Hv + c0];
            float4 h1 = *(const float4*)&hidden[row*Hv + c0 + 4];
            float v[8];
            unpack2(acc[r][0], v[0], v[1]); unpack2(acc[r][1], v[2], v[3]);
            unpack2(acc[r][2], v[4], v[5]); unpack2(acc[r][3], v[6], v[7]);
            x[0] = v[0]+b20.x+h0.x; x[1] = v[1]+b20.y+h0.y;
            x[2] = v[2]+b20.z+h0.z; x[3] = v[3]+b20.w+h0.w;
            x[4] = v[4]+b21.x+h1.x; x[5] = v[5]+b21.y+h1.y;
            x[6] = v[6]+b21.z+h1.z; x[7] = v[7]+b21.w+h1.w;
        } else {
            #pragma unroll
            for (int j = 0; j < 8; j++) x[j] = 0.f;
        }
        float s = 0.f, ss = 0.f;
        #pragma unroll
        for (int j = 0; j < 8; j++) { s += x[j]; ss += x[j]*x[j]; }
        #pragma unroll
        for (int off = 8; off > 0; off >>= 1) {
            s  += __shfl_xor_sync(0xffffffffu, s, off);
            ss += __shfl_xor_sync(0xffffffffu, ss, off);
        }
        if (row < BN) {
            float mean = s * (1.f/128.f);
            float var  = ss * (1.f/128.f) - mean*mean;
            float rstd = rsqrtf(var + EPSv);
            float4 o0, o1;
            o0.x = (x[0]-mean)*rstd*gv0.x + be0.x;
            o0.y = (x[1]-mean)*rstd*gv0.y + be0.y;
            o0.z = (x[2]-mean)*rstd*gv0.z + be0.z;
            o0.w = (x[3]-mean)*rstd*gv0.w + be0.w;
            o1.x = (x[4]-mean)*rstd*gv1.x + be1.x;
            o1.y = (x[5]-mean)*rstd*gv1.y + be1.y;
            o1.z = (x[6]-mean)*rstd*gv1.z + be1.z;
            o1.w = (x[7]-mean)*rstd*gv1.w + be1.w;
            *(float4*)&out[row*Hv + c0]     = o0;
            *(float4*)&out[row*Hv + c0 + 4] = o1;
        }
    }
}

// ---------------- launch ----------------
extern "C" void kernel_launch(void* const* d_in, const int* in_sizes, int n_in,
                              void* d_out, int out_size)
{
    const float* hidden = (const float*)d_in[0];
    const float* temb   = (const float*)d_in[1];
    const int*   eidx   = (const int*)d_in[2];
    const int*   etype  = (const int*)d_in[3];
    const float* eemb   = (const float*)d_in[4];
    const float* Wq = (const float*)d_in[5];  const float* bq = (const float*)d_in[6];
    const float* Wk = (const float*)d_in[7];  const float* bk = (const float*)d_in[8];
    const float* Wv = (const float*)d_in[9];  const float* bv = (const float*)d_in[10];
    const float* We = (const float*)d_in[11]; const float* be = (const float*)d_in[12];
    const float* W1 = (const float*)d_in[13]; const float* b1 = (const float*)d_in[14];
    const float* W2 = (const float*)d_in[15]; const float* b2 = (const float*)d_in[16];
    const float* gamma = (const float*)d_in[17]; const float* beta = (const float*)d_in[18];
    float* out = (float*)d_out;

    int gb = (BN + TM - 1)/TM;   // 313
    zero_init<<<2560, 256>>>();
    prep_edge<<<1, 1024>>>(eemb, Wk, Wv, We, be);
    dim3 gq(gb, 1, 3);
    gemm_qkv<<<gq, 128>>>(hidden, temb, Wq, bq, Wk, bk, Wv, bv);
    edge_fused<<<Ev/8, 256>>>(eidx, etype);
    gemm_mlp1<<<gb, 128>>>(hidden, temb, W1, b1);
    gemm2_ln<<<gb, 128>>>(hidden, W2, b2, gamma, beta, out);
}

// round 12
// speedup vs baseline: 1.6202x; 1.0489x over previous
#include <cuda_runtime.h>
#include <math.h>
#include <stdint.h>

typedef unsigned long long ull;

#define Bv 2
#define Nv 10000
#define Ev 160000
#define Hv 128
#define ETv 8
#define BN (Bv*Nv)          // 20000
#define EPSv 1e-5f
#define RSQRT_H 0.08838834764831843f

// ---------------- scratch ----------------
// Q/K/V/Agg are batch-interleaved: index (node*2 + batch)*Hv
__device__ float g_Q[BN*Hv];
__device__ float g_K[BN*Hv];
__device__ float g_V[BN*Hv];
__device__ float g_Agg[BN*Hv];
__device__ float g_Hpart[BN*Hv];   // mlp1 hidden+temb partial (row-major, non-interleaved)
__device__ float g_Hmid[BN*Hv];
__device__ float g_segsum[BN];     // node*2 + batch
__device__ float g_Ke[ETv*Hv];
__device__ float g_Ve[ETv*Hv];
__device__ float g_eL[ETv];

// row (b*Nv+node) -> interleaved row (node*2+b)
__device__ __forceinline__ int irow_of(int row) {
    int b = row >= Nv;
    return (row - b*Nv)*2 + b;
}

// ---------------- helpers ----------------
__device__ __forceinline__ void red_add_v4(float* p, float4 v) {
    asm volatile("red.global.add.v4.f32 [%0], {%1,%2,%3,%4};"
                 :: "l"(p), "f"(v.x), "f"(v.y), "f"(v.z), "f"(v.w) : "memory");
}
__device__ __forceinline__ void fma2(ull& d, ull a, ull b) {
    asm("fma.rn.f32x2 %0, %1, %2, %0;" : "+l"(d) : "l"(a), "l"(b));
}
__device__ __forceinline__ ull dup2(float v) {
    ull r; unsigned u = __float_as_uint(v);
    asm("mov.b64 %0, {%1, %1};" : "=l"(r) : "r"(u));
    return r;
}
__device__ __forceinline__ void unpack2(ull v, float& lo, float& hi) {
    unsigned a, b;
    asm("mov.b64 {%0, %1}, %2;" : "=r"(a), "=r"(b) : "l"(v));
    lo = __uint_as_float(a); hi = __uint_as_float(b);
}
__device__ __forceinline__ float4 ldg4(const float* p) {
    return __ldg((const float4*)p);
}

// ---------------- 0: zero scratch ----------------
__global__ void zero_init() {
    int i = blockIdx.x * blockDim.x + threadIdx.x;
    int stride = gridDim.x * blockDim.x;
    for (int j = i; j < BN*Hv; j += stride) g_Agg[j] = 0.0f;
    for (int j = i; j < BN; j += stride) g_segsum[j] = 0.0f;
}

// ---------------- 1: edge-type projections (tiny) ----------------
__global__ void prep_edge(const float* __restrict__ eemb,
                          const float* __restrict__ Wk,
                          const float* __restrict__ Wv,
                          const float* __restrict__ We,
                          const float* __restrict__ be) {
    int t = threadIdx.x >> 7;
    int j = threadIdx.x & 127;
    float ake = 0.f, ave = 0.f;
    #pragma unroll 4
    for (int k = 0; k < Hv; k++) {
        float e = eemb[t*Hv + k];
        ake += e * Wk[k*Hv + j];
        ave += e * Wv[k*Hv + j];
    }
    g_Ke[t*Hv + j] = ake;
    g_Ve[t*Hv + j] = ave;
    if (j == 0) {
        float s = 0.f;
        for (int k = 0; k < Hv; k++) s += eemb[t*Hv + k] * We[k];
        g_eL[t] = s + be[0];
    }
}

// ================= R2-style f32x2 GEMM framework =================
#define TM 64
#define KC 32
#define APAD 36

__device__ __forceinline__ void mm_chunk(const float* As, const float* Ws,
                                         int r0, int c0,
                                         ull acc[8][4]) {
    #pragma unroll
    for (int k = 0; k < KC; k++) {
        ulonglong2 b0 = *(const ulonglong2*)&Ws[k*Hv + c0];
        ulonglong2 b1 = *(const ulonglong2*)&Ws[k*Hv + c0 + 4];
        #pragma unroll
        for (int r = 0; r < 8; r++) {
            ull aa = dup2(As[(r0 + r)*APAD + k]);
            fma2(acc[r][0], aa, b0.x);
            fma2(acc[r][1], aa, b0.y);
            fma2(acc[r][2], aa, b1.x);
            fma2(acc[r][3], aa, b1.y);
        }
    }
}

__device__ __forceinline__ void load_w(const float* __restrict__ W, int k0,
                                       float* Ws, int tid) {
    #pragma unroll
    for (int i = 0; i < 8; i++) {
        int lin = tid + i*128;
        int wr = lin >> 5; int wc = (lin & 31) * 4;
        *(float4*)&Ws[wr*Hv + wc] = *(const float4*)&W[(k0 + wr)*Hv + wc];
    }
}

// ---------------- 2: QKV GEMM (z selects Q/K/V) ----------------
__global__ void __launch_bounds__(128)
gemm_qkv(const float* __restrict__ hidden, const float* __restrict__ temb,
         const float* __restrict__ Wq, const float* __restrict__ bq,
         const float* __restrict__ Wk, const float* __restrict__ bk,
         const float* __restrict__ Wv, const float* __restrict__ bv)
{
    int which = blockIdx.z;
    const float* W    = which == 0 ? Wq : (which == 1 ? Wk : Wv);
    const float* bias = which == 0 ? bq : (which == 1 ? bk : bv);
    float* out        = which == 0 ? g_Q : (which == 1 ? g_K : g_V);
    bool addT = (which < 2);

    __shared__ float As[TM*APAD];
    __shared__ float Ws[KC*Hv];
    int tid = threadIdx.x;
    int rg = tid >> 4, cg = tid & 15;
    int r0 = rg * 8, c0 = cg * 8;
    int row0 = blockIdx.x * TM;

    ull acc[8][4];
    #pragma unroll
    for (int r = 0; r < 8; r++)
        #pragma unroll
        for (int c = 0; c < 4; c++) acc[r][c] = 0ull;

    for (int k0 = 0; k0 < Hv; k0 += KC) {
        #pragma unroll
        for (int i = 0; i < 4; i++) {
            int lin = tid + i*128;
            int r = lin >> 3; int kk = (lin & 7) * 4;
            int row = row0 + r;
            float4 a = make_float4(0.f,0.f,0.f,0.f);
            if (row < BN) {
                a = *(const float4*)&hidden[row*Hv + k0 + kk];
                if (addT) {
                    float4 b = *(const float4*)&temb[row*Hv + k0 + kk];
                    a.x += b.x; a.y += b.y; a.z += b.z; a.w += b.w;
                }
            }
            *(float4*)&As[r*APAD + kk] = a;
        }
        load_w(W, k0, Ws, tid);
        __syncthreads();
        mm_chunk(As, Ws, r0, c0, acc);
        __syncthreads();
    }
    float4 bi0 = *(const float4*)&bias[c0];
    float4 bi1 = *(const float4*)&bias[c0 + 4];
    #pragma unroll
    for (int r = 0; r < 8; r++) {
        int row = row0 + r0 + r;
        if (row < BN) {
            int ir = irow_of(row);
            float v0,v1,v2,v3,v4,v5,v6,v7;
            unpack2(acc[r][0], v0, v1); unpack2(acc[r][1], v2, v3);
            unpack2(acc[r][2], v4, v5); unpack2(acc[r][3], v6, v7);
            *(float4*)&out[ir*Hv + c0] =
                make_float4(v0+bi0.x, v1+bi0.y, v2+bi0.z, v3+bi0.w);
            *(float4*)&out[ir*Hv + c0 + 4] =
                make_float4(v4+bi1.x, v5+bi1.y, v6+bi1.z, v7+bi1.w);
        }
    }
}

// ---------------- 3: FUSED edge kernel (interleaved gathers) ----------------
__global__ void edge_fused(const int* __restrict__ eidx, const int* __restrict__ etype)
{
    int w = (blockIdx.x * blockDim.x + threadIdx.x) >> 5;
    int lane = threadIdx.x & 31;
    if (w >= Ev) return;
    int src = eidx[w];
    int tgt = eidx[Ev + w];
    int ty  = etype[w];
    float4 ke = ldg4(&g_Ke[ty*Hv + lane*4]);
    float4 ve = ldg4(&g_Ve[ty*Hv + lane*4]);
    float el = __ldg(&g_eL[ty]);

    const float* qb = &g_Q[(tgt*2)*Hv + lane*4];
    const float* kb = &g_K[(src*2)*Hv + lane*4];
    float4 q0 = ldg4(qb);
    float4 k0 = ldg4(kb);
    float4 q1 = ldg4(qb + Hv);
    float4 k1 = ldg4(kb + Hv);

    float s0 = q0.x*(k0.x+ke.x) + q0.y*(k0.y+ke.y) + q0.z*(k0.z+ke.z) + q0.w*(k0.w+ke.w);
    float s1 = q1.x*(k1.x+ke.x) + q1.y*(k1.y+ke.y) + q1.z*(k1.z+ke.z) + q1.w*(k1.w+ke.w);
    #pragma unroll
    for (int off = 16; off > 0; off >>= 1) {
        s0 += __shfl_xor_sync(0xffffffffu, s0, off);
        s1 += __shfl_xor_sync(0xffffffffu, s1, off);
    }
    float ex0 = expf(s0 * RSQRT_H + el);
    float ex1 = expf(s1 * RSQRT_H + el);
    if (lane == 0) {
        atomicAdd(&g_segsum[tgt*2],     ex0);
        atomicAdd(&g_segsum[tgt*2 + 1], ex1);
    }
    const float* vb = &g_V[(src*2)*Hv + lane*4];
    float4 v0 = ldg4(vb);
    float4 v1 = ldg4(vb + Hv);
    float4 a0 = make_float4(ex0*(v0.x+ve.x), ex0*(v0.y+ve.y),
                            ex0*(v0.z+ve.z), ex0*(v0.w+ve.w));
    float4 a1 = make_float4(ex1*(v1.x+ve.x), ex1*(v1.y+ve.y),
                            ex1*(v1.z+ve.z), ex1*(v1.w+ve.w));
    float* ab = &g_Agg[(tgt*2)*Hv + lane*4];
    red_add_v4(ab, a0);
    red_add_v4(ab + Hv, a1);
}

// ---------------- 4a: MLP1 hidden+temb partial (independent of edge phase) ----------------
__global__ void __launch_bounds__(128)
gemm_mlp1_ht(const float* __restrict__ hidden, const float* __restrict__ temb,
             const float* __restrict__ W1)
{
    __shared__ float As[TM*APAD];
    __shared__ float Ws[KC*Hv];
    int tid = threadIdx.x;
    int rg = tid >> 4, cg = tid & 15;
    int r0 = rg * 8, c0 = cg * 8;
    int row0 = blockIdx.x * TM;

    ull acc[8][4];
    #pragma unroll
    for (int r = 0; r < 8; r++)
        #pragma unroll
        for (int c = 0; c < 4; c++) acc[r][c] = 0ull;

    #pragma unroll
    for (int half = 0; half < 2; half++) {
        const float* S  = half ? temb : hidden;
        const float* Wc = W1 + (half ? 2 : 0) * 128 * Hv;
        for (int k0 = 0; k0 < Hv; k0 += KC) {
            #pragma unroll
            for (int i = 0; i < 4; i++) {
                int lin = tid + i*128;
                int r = lin >> 3; int kk = (lin & 7) * 4;
                int row = row0 + r;
                float4 a = make_float4(0.f,0.f,0.f,0.f);
                if (row < BN) a = *(const float4*)&S[row*Hv + k0 + kk];
                *(float4*)&As[r*APAD + kk] = a;
            }
            load_w(Wc, k0, Ws, tid);
            __syncthreads();
            mm_chunk(As, Ws, r0, c0, acc);
            __syncthreads();
        }
    }
    #pragma unroll
    for (int r = 0; r < 8; r++) {
        int row = row0 + r0 + r;
        if (row < BN) {
            float v[8];
            unpack2(acc[r][0], v[0], v[1]); unpack2(acc[r][1], v[2], v[3]);
            unpack2(acc[r][2], v[4], v[5]); unpack2(acc[r][3], v[6], v[7]);
            *(float4*)&g_Hpart[row*Hv + c0]     = make_float4(v[0],v[1],v[2],v[3]);
            *(float4*)&g_Hpart[row*Hv + c0 + 4] = make_float4(v[4],v[5],v[6],v[7]);
        }
    }
}

// ---------------- 4b: MLP1 Agg chunk + combine + SiLU ----------------
__global__ void __launch_bounds__(128)
gemm_mlp1_agg(const float* __restrict__ W1, const float* __restrict__ b1)
{
    __shared__ float As[TM*APAD];
    __shared__ float Ws[KC*Hv];
    int tid = threadIdx.x;
    int rg = tid >> 4, cg = tid & 15;
    int r0 = rg * 8, c0 = cg * 8;
    int row0 = blockIdx.x * TM;
    const float* Wc = W1 + 128 * Hv;   // agg chunk rows

    ull acc[8][4];
    #pragma unroll
    for (int r = 0; r < 8; r++)
        #pragma unroll
        for (int c = 0; c < 4; c++) acc[r][c] = 0ull;

    for (int k0 = 0; k0 < Hv; k0 += KC) {
        #pragma unroll
        for (int i = 0; i < 4; i++) {
            int lin = tid + i*128;
            int r = lin >> 3; int kk = (lin & 7) * 4;
            int row = row0 + r;
            float4 a = make_float4(0.f,0.f,0.f,0.f);
            if (row < BN) {
                int ir = irow_of(row);
                a = *(const float4*)&g_Agg[ir*Hv + k0 + kk];
                float s = g_segsum[ir];
                float inv = (s > 0.f) ? 1.f/s : 0.f;
                a.x *= inv; a.y *= inv; a.z *= inv; a.w *= inv;
            }
            *(float4*)&As[r*APAD + kk] = a;
        }
        load_w(Wc, k0, Ws, tid);
        __syncthreads();
        mm_chunk(As, Ws, r0, c0, acc);
        __syncthreads();
    }
    float4 bi0 = *(const float4*)&b1[c0];
    float4 bi1 = *(const float4*)&b1[c0 + 4];
    #pragma unroll
    for (int r = 0; r < 8; r++) {
        int row = row0 + r0 + r;
        if (row < BN) {
            float4 p0 = *(const float4*)&g_Hpart[row*Hv + c0];
            float4 p1 = *(const float4*)&g_Hpart[row*Hv + c0 + 4];
            float v[8];
            unpack2(acc[r][0], v[0], v[1]); unpack2(acc[r][1], v[2], v[3]);
            unpack2(acc[r][2], v[4], v[5]); unpack2(acc[r][3], v[6], v[7]);
            v[0]+=bi0.x+p0.x; v[1]+=bi0.y+p0.y; v[2]+=bi0.z+p0.z; v[3]+=bi0.w+p0.w;
            v[4]+=bi1.x+p1.x; v[5]+=bi1.y+p1.y; v[6]+=bi1.z+p1.z; v[7]+=bi1.w+p1.w;
            #pragma unroll
            for (int j = 0; j < 8; j++) v[j] = v[j] / (1.f + expf(-v[j]));
            *(float4*)&g_Hmid[row*Hv + c0]     = make_float4(v[0],v[1],v[2],v[3]);
            *(float4*)&g_Hmid[row*Hv + c0 + 4] = make_float4(v[4],v[5],v[6],v[7]);
        }
    }
}

// ---------------- 5: GEMM2 + residual + LayerNorm ----------------
__global__ void __launch_bounds__(128)
gemm2_ln(const float* __restrict__ hidden,
         const float* __restrict__ W2, const float* __restrict__ b2,
         const float* __restrict__ gamma, const float* __restrict__ beta,
         float* __restrict__ out)
{
    __shared__ float As[TM*APAD];
    __shared__ float Ws[KC*Hv];
    int tid = threadIdx.x;
    int rg = tid >> 4, cg = tid & 15;
    int r0 = rg * 8, c0 = cg * 8;
    int row0 = blockIdx.x * TM;

    ull acc[8][4];
    #pragma unroll
    for (int r = 0; r < 8; r++)
        #pragma unroll
        for (int c = 0; c < 4; c++) acc[r][c] = 0ull;

    for (int k0 = 0; k0 < Hv; k0 += KC) {
        #pragma unroll
        for (int i = 0; i < 4; i++) {
            int lin = tid + i*128;
            int r = lin >> 3; int kk = (lin & 7) * 4;
            int row = row0 + r;
            float4 a = make_float4(0.f,0.f,0.f,0.f);
            if (row < BN) a = *(const float4*)&g_Hmid[row*Hv + k0 + kk];
            *(float4*)&As[r*APAD + kk] = a;
        }
        load_w(W2, k0, Ws, tid);
        __syncthreads();
        mm_chunk(As, Ws, r0, c0, acc);
        __syncthreads();
    }

    float4 b20 = *(const float4*)&b2[c0];
    float4 b21 = *(const float4*)&b2[c0 + 4];
    float4 gv0 = *(const float4*)&gamma[c0];
    float4 gv1 = *(const float4*)&gamma[c0 + 4];
    float4 be0 = *(const float4*)&beta[c0];
    float4 be1 = *(const float4*)&beta[c0 + 4];

    #pragma unroll
    for (int r = 0; r < 8; r++) {
        int row = row0 + r0 + r;
        float x[8];
        if (row < BN) {
            float4 h0 = *(const float4*)&hidden[row*Hv + c0];
            float4 h1 = *(const float4*)&hidden[row*Hv + c0 + 4];
            float v[8];
            unpack2(acc[r][0], v[0], v[1]); unpack2(acc[r][1], v[2], v[3]);
            unpack2(acc[r][2], v[4], v[5]); unpack2(acc[r][3], v[6], v[7]);
            x[0] = v[0]+b20.x+h0.x; x[1] = v[1]+b20.y+h0.y;
            x[2] = v[2]+b20.z+h0.z; x[3] = v[3]+b20.w+h0.w;
            x[4] = v[4]+b21.x+h1.x; x[5] = v[5]+b21.y+h1.y;
            x[6] = v[6]+b21.z+h1.z; x[7] = v[7]+b21.w+h1.w;
        } else {
            #pragma unroll
            for (int j = 0; j < 8; j++) x[j] = 0.f;
        }
        float s = 0.f, ss = 0.f;
        #pragma unroll
        for (int j = 0; j < 8; j++) { s += x[j]; ss += x[j]*x[j]; }
        #pragma unroll
        for (int off = 8; off > 0; off >>= 1) {
            s  += __shfl_xor_sync(0xffffffffu, s, off);
            ss += __shfl_xor_sync(0xffffffffu, ss, off);
        }
        if (row < BN) {
            float mean = s * (1.f/128.f);
            float var  = ss * (1.f/128.f) - mean*mean;
            float rstd = rsqrtf(var + EPSv);
            float4 o0, o1;
            o0.x = (x[0]-mean)*rstd*gv0.x + be0.x;
            o0.y = (x[1]-mean)*rstd*gv0.y + be0.y;
            o0.z = (x[2]-mean)*rstd*gv0.z + be0.z;
            o0.w = (x[3]-mean)*rstd*gv0.w + be0.w;
            o1.x = (x[4]-mean)*rstd*gv1.x + be1.x;
            o1.y = (x[5]-mean)*rstd*gv1.y + be1.y;
            o1.z = (x[6]-mean)*rstd*gv1.z + be1.z;
            o1.w = (x[7]-mean)*rstd*gv1.w + be1.w;
            *(float4*)&out[row*Hv + c0]     = o0;
            *(float4*)&out[row*Hv + c0 + 4] = o1;
        }
    }
}

// ---------------- launch (two-stream fork/join, capture-safe) ----------------
extern "C" void kernel_launch(void* const* d_in, const int* in_sizes, int n_in,
                              void* d_out, int out_size)
{
    const float* hidden = (const float*)d_in[0];
    const float* temb   = (const float*)d_in[1];
    const int*   eidx   = (const int*)d_in[2];
    const int*   etype  = (const int*)d_in[3];
    const float* eemb   = (const float*)d_in[4];
    const float* Wq = (const float*)d_in[5];  const float* bq = (const float*)d_in[6];
    const float* Wk = (const float*)d_in[7];  const float* bk = (const float*)d_in[8];
    const float* Wv = (const float*)d_in[9];  const float* bv = (const float*)d_in[10];
    const float* We = (const float*)d_in[11]; const float* be = (const float*)d_in[12];
    const float* W1 = (const float*)d_in[13]; const float* b1 = (const float*)d_in[14];
    const float* W2 = (const float*)d_in[15]; const float* b2 = (const float*)d_in[16];
    const float* gamma = (const float*)d_in[17]; const float* beta = (const float*)d_in[18];
    float* out = (float*)d_out;

    int gb = (BN + TM - 1)/TM;   // 313

    cudaStream_t s1;
    cudaStreamCreateWithFlags(&s1, cudaStreamNonBlocking);
    cudaEvent_t eFork, ePrep, eQkv, eHt;
    cudaEventCreateWithFlags(&eFork, cudaEventDisableTiming);
    cudaEventCreateWithFlags(&ePrep, cudaEventDisableTiming);
    cudaEventCreateWithFlags(&eQkv,  cudaEventDisableTiming);
    cudaEventCreateWithFlags(&eHt,   cudaEventDisableTiming);

    // fork s1 off the main (capture) stream
    cudaEventRecord(eFork, 0);
    cudaStreamWaitEvent(s1, eFork, 0);

    // s1: zero + edge-type prep (concurrent with QKV GEMM below)
    zero_init<<<2560, 256, 0, s1>>>();
    prep_edge<<<1, 1024, 0, s1>>>(eemb, Wk, Wv, We, be);
    cudaEventRecord(ePrep, s1);

    // main: QKV GEMM
    dim3 gq(gb, 1, 3);
    gemm_qkv<<<gq, 128>>>(hidden, temb, Wq, bq, Wk, bk, Wv, bv);
    cudaEventRecord(eQkv, 0);

    // s1: mlp1 hidden+temb partial (concurrent with edge_fused)
    cudaStreamWaitEvent(s1, eQkv, 0);
    gemm_mlp1_ht<<<gb, 128, 0, s1>>>(hidden, temb, W1);
    cudaEventRecord(eHt, s1);

    // main: edge phase (needs zero_init + prep_edge complete)
    cudaStreamWaitEvent(0, ePrep, 0);
    edge_fused<<<Ev/8, 256>>>(eidx, etype);

    // join: mlp1 agg-chunk combine, then output GEMM
    cudaStreamWaitEvent(0, eHt, 0);
    gemm_mlp1_agg<<<gb, 128>>>(W1, b1);
    gemm2_ln<<<gb, 128>>>(hidden, W2, b2, gamma, beta, out);

    cudaEventDestroy(eFork);
    cudaEventDestroy(ePrep);
    cudaEventDestroy(eQkv);
    cudaEventDestroy(eHt);
    cudaStreamDestroy(s1);
}

// round 13
// speedup vs baseline: 1.6394x; 1.0119x over previous
#include <cuda_runtime.h>
#include <math.h>
#include <stdint.h>

typedef unsigned long long ull;

#define Bv 2
#define Nv 10000
#define Ev 160000
#define Hv 128
#define ETv 8
#define BN (Bv*Nv)          // 20000
#define EPSv 1e-5f
#define RSQRT_H 0.08838834764831843f

// ---------------- scratch ----------------
// Q/K/V/Agg are batch-interleaved: index (node*2 + batch)*Hv
__device__ float g_Q[BN*Hv];
__device__ float g_K[BN*Hv];
__device__ float g_V[BN*Hv];
__device__ float g_Agg[BN*Hv];
__device__ float g_Hpart[BN*Hv];   // mlp1 hidden+temb partial (row-major, non-interleaved)
__device__ float g_Hmid[BN*Hv];
__device__ float g_segsum[BN];     // node*2 + batch
__device__ float g_Ke[ETv*Hv];
__device__ float g_Ve[ETv*Hv];
__device__ float g_eL[ETv];

// row (b*Nv+node) -> interleaved row (node*2+b)
__device__ __forceinline__ int irow_of(int row) {
    int b = row >= Nv;
    return (row - b*Nv)*2 + b;
}

// ---------------- helpers ----------------
__device__ __forceinline__ void red_add_v4(float* p, float4 v) {
    asm volatile("red.global.add.v4.f32 [%0], {%1,%2,%3,%4};"
                 :: "l"(p), "f"(v.x), "f"(v.y), "f"(v.z), "f"(v.w) : "memory");
}
__device__ __forceinline__ void fma2(ull& d, ull a, ull b) {
    asm("fma.rn.f32x2 %0, %1, %2, %0;" : "+l"(d) : "l"(a), "l"(b));
}
__device__ __forceinline__ ull dup2(float v) {
    ull r; unsigned u = __float_as_uint(v);
    asm("mov.b64 %0, {%1, %1};" : "=l"(r) : "r"(u));
    return r;
}
__device__ __forceinline__ void unpack2(ull v, float& lo, float& hi) {
    unsigned a, b;
    asm("mov.b64 {%0, %1}, %2;" : "=r"(a), "=r"(b) : "l"(v));
    lo = __uint_as_float(a); hi = __uint_as_float(b);
}
__device__ __forceinline__ float4 ldg4(const float* p) {
    return __ldg((const float4*)p);
}

// ---------------- 0: zero scratch ----------------
__global__ void zero_init() {
    int i = blockIdx.x * blockDim.x + threadIdx.x;
    int stride = gridDim.x * blockDim.x;
    for (int j = i; j < BN*Hv; j += stride) g_Agg[j] = 0.0f;
    for (int j = i; j < BN; j += stride) g_segsum[j] = 0.0f;
}

// ---------------- 1: edge-type projections (tiny) ----------------
__global__ void prep_edge(const float* __restrict__ eemb,
                          const float* __restrict__ Wk,
                          const float* __restrict__ Wv,
                          const float* __restrict__ We,
                          const float* __restrict__ be) {
    int t = threadIdx.x >> 7;
    int j = threadIdx.x & 127;
    float ake = 0.f, ave = 0.f;
    #pragma unroll 4
    for (int k = 0; k < Hv; k++) {
        float e = eemb[t*Hv + k];
        ake += e * Wk[k*Hv + j];
        ave += e * Wv[k*Hv + j];
    }
    g_Ke[t*Hv + j] = ake;
    g_Ve[t*Hv + j] = ave;
    if (j == 0) {
        float s = 0.f;
        for (int k = 0; k < Hv; k++) s += eemb[t*Hv + k] * We[k];
        g_eL[t] = s + be[0];
    }
}

// ================= R2-style f32x2 GEMM framework =================
#define TM 64
#define KC 32
#define APAD 36

__device__ __forceinline__ void mm_chunk(const float* As, const float* Ws,
                                         int r0, int c0,
                                         ull acc[8][4]) {
    #pragma unroll
    for (int k = 0; k < KC; k++) {
        ulonglong2 b0 = *(const ulonglong2*)&Ws[k*Hv + c0];
        ulonglong2 b1 = *(const ulonglong2*)&Ws[k*Hv + c0 + 4];
        #pragma unroll
        for (int r = 0; r < 8; r++) {
            ull aa = dup2(As[(r0 + r)*APAD + k]);
            fma2(acc[r][0], aa, b0.x);
            fma2(acc[r][1], aa, b0.y);
            fma2(acc[r][2], aa, b1.x);
            fma2(acc[r][3], aa, b1.y);
        }
    }
}

__device__ __forceinline__ void load_w(const float* __restrict__ W, int k0,
                                       float* Ws, int tid) {
    #pragma unroll
    for (int i = 0; i < 8; i++) {
        int lin = tid + i*128;
        int wr = lin >> 5; int wc = (lin & 31) * 4;
        *(float4*)&Ws[wr*Hv + wc] = *(const float4*)&W[(k0 + wr)*Hv + wc];
    }
}

// ---------------- 2: QKV GEMM (z selects Q/K/V) ----------------
__global__ void __launch_bounds__(128)
gemm_qkv(const float* __restrict__ hidden, const float* __restrict__ temb,
         const float* __restrict__ Wq, const float* __restrict__ bq,
         const float* __restrict__ Wk, const float* __restrict__ bk,
         const float* __restrict__ Wv, const float* __restrict__ bv)
{
    int which = blockIdx.z;
    const float* W    = which == 0 ? Wq : (which == 1 ? Wk : Wv);
    const float* bias = which == 0 ? bq : (which == 1 ? bk : bv);
    float* out        = which == 0 ? g_Q : (which == 1 ? g_K : g_V);
    bool addT = (which < 2);

    __shared__ float As[TM*APAD];
    __shared__ float Ws[KC*Hv];
    int tid = threadIdx.x;
    int rg = tid >> 4, cg = tid & 15;
    int r0 = rg * 8, c0 = cg * 8;
    int row0 = blockIdx.x * TM;

    ull acc[8][4];
    #pragma unroll
    for (int r = 0; r < 8; r++)
        #pragma unroll
        for (int c = 0; c < 4; c++) acc[r][c] = 0ull;

    for (int k0 = 0; k0 < Hv; k0 += KC) {
        #pragma unroll
        for (int i = 0; i < 4; i++) {
            int lin = tid + i*128;
            int r = lin >> 3; int kk = (lin & 7) * 4;
            int row = row0 + r;
            float4 a = make_float4(0.f,0.f,0.f,0.f);
            if (row < BN) {
                a = *(const float4*)&hidden[row*Hv + k0 + kk];
                if (addT) {
                    float4 b = *(const float4*)&temb[row*Hv + k0 + kk];
                    a.x += b.x; a.y += b.y; a.z += b.z; a.w += b.w;
                }
            }
            *(float4*)&As[r*APAD + kk] = a;
        }
        load_w(W, k0, Ws, tid);
        __syncthreads();
        mm_chunk(As, Ws, r0, c0, acc);
        __syncthreads();
    }
    float4 bi0 = *(const float4*)&bias[c0];
    float4 bi1 = *(const float4*)&bias[c0 + 4];
    #pragma unroll
    for (int r = 0; r < 8; r++) {
        int row = row0 + r0 + r;
        if (row < BN) {
            int ir = irow_of(row);
            float v0,v1,v2,v3,v4,v5,v6,v7;
            unpack2(acc[r][0], v0, v1); unpack2(acc[r][1], v2, v3);
            unpack2(acc[r][2], v4, v5); unpack2(acc[r][3], v6, v7);
            *(float4*)&out[ir*Hv + c0] =
                make_float4(v0+bi0.x, v1+bi0.y, v2+bi0.z, v3+bi0.w);
            *(float4*)&out[ir*Hv + c0 + 4] =
                make_float4(v4+bi1.x, v5+bi1.y, v6+bi1.z, v7+bi1.w);
        }
    }
}

// ---------------- 3: FUSED edge kernel (interleaved gathers) ----------------
__global__ void edge_fused(const int* __restrict__ eidx, const int* __restrict__ etype)
{
    int w = (blockIdx.x * blockDim.x + threadIdx.x) >> 5;
    int lane = threadIdx.x & 31;
    if (w >= Ev) return;
    int src = eidx[w];
    int tgt = eidx[Ev + w];
    int ty  = etype[w];
    float4 ke = ldg4(&g_Ke[ty*Hv + lane*4]);
    float4 ve = ldg4(&g_Ve[ty*Hv + lane*4]);
    float el = __ldg(&g_eL[ty]);

    const float* qb = &g_Q[(tgt*2)*Hv + lane*4];
    const float* kb = &g_K[(src*2)*Hv + lane*4];
    float4 q0 = ldg4(qb);
    float4 k0 = ldg4(kb);
    float4 q1 = ldg4(qb + Hv);
    float4 k1 = ldg4(kb + Hv);

    float s0 = q0.x*(k0.x+ke.x) + q0.y*(k0.y+ke.y) + q0.z*(k0.z+ke.z) + q0.w*(k0.w+ke.w);
    float s1 = q1.x*(k1.x+ke.x) + q1.y*(k1.y+ke.y) + q1.z*(k1.z+ke.z) + q1.w*(k1.w+ke.w);
    #pragma unroll
    for (int off = 16; off > 0; off >>= 1) {
        s0 += __shfl_xor_sync(0xffffffffu, s0, off);
        s1 += __shfl_xor_sync(0xffffffffu, s1, off);
    }
    float ex0 = expf(s0 * RSQRT_H + el);
    float ex1 = expf(s1 * RSQRT_H + el);
    if (lane == 0) {
        atomicAdd(&g_segsum[tgt*2],     ex0);
        atomicAdd(&g_segsum[tgt*2 + 1], ex1);
    }
    const float* vb = &g_V[(src*2)*Hv + lane*4];
    float4 v0 = ldg4(vb);
    float4 v1 = ldg4(vb + Hv);
    float4 a0 = make_float4(ex0*(v0.x+ve.x), ex0*(v0.y+ve.y),
                            ex0*(v0.z+ve.z), ex0*(v0.w+ve.w));
    float4 a1 = make_float4(ex1*(v1.x+ve.x), ex1*(v1.y+ve.y),
                            ex1*(v1.z+ve.z), ex1*(v1.w+ve.w));
    float* ab = &g_Agg[(tgt*2)*Hv + lane*4];
    red_add_v4(ab, a0);
    red_add_v4(ab + Hv, a1);
}

// ---------------- 4a: MLP1 hidden+temb partial (independent of edge phase) ----------------
__global__ void __launch_bounds__(128)
gemm_mlp1_ht(const float* __restrict__ hidden, const float* __restrict__ temb,
             const float* __restrict__ W1)
{
    __shared__ float As[TM*APAD];
    __shared__ float Ws[KC*Hv];
    int tid = threadIdx.x;
    int rg = tid >> 4, cg = tid & 15;
    int r0 = rg * 8, c0 = cg * 8;
    int row0 = blockIdx.x * TM;

    ull acc[8][4];
    #pragma unroll
    for (int r = 0; r < 8; r++)
        #pragma unroll
        for (int c = 0; c < 4; c++) acc[r][c] = 0ull;

    #pragma unroll
    for (int half = 0; half < 2; half++) {
        const float* S  = half ? temb : hidden;
        const float* Wc = W1 + (half ? 2 : 0) * 128 * Hv;
        for (int k0 = 0; k0 < Hv; k0 += KC) {
            #pragma unroll
            for (int i = 0; i < 4; i++) {
                int lin = tid + i*128;
                int r = lin >> 3; int kk = (lin & 7) * 4;
                int row = row0 + r;
                float4 a = make_float4(0.f,0.f,0.f,0.f);
                if (row < BN) a = *(const float4*)&S[row*Hv + k0 + kk];
                *(float4*)&As[r*APAD + kk] = a;
            }
            load_w(Wc, k0, Ws, tid);
            __syncthreads();
            mm_chunk(As, Ws, r0, c0, acc);
            __syncthreads();
        }
    }
    #pragma unroll
    for (int r = 0; r < 8; r++) {
        int row = row0 + r0 + r;
        if (row < BN) {
            float v[8];
            unpack2(acc[r][0], v[0], v[1]); unpack2(acc[r][1], v[2], v[3]);
            unpack2(acc[r][2], v[4], v[5]); unpack2(acc[r][3], v[6], v[7]);
            *(float4*)&g_Hpart[row*Hv + c0]     = make_float4(v[0],v[1],v[2],v[3]);
            *(float4*)&g_Hpart[row*Hv + c0 + 4] = make_float4(v[4],v[5],v[6],v[7]);
        }
    }
}

// ---------------- 4b: MLP1 Agg chunk + combine + SiLU ----------------
__global__ void __launch_bounds__(128)
gemm_mlp1_agg(const float* __restrict__ W1, const float* __restrict__ b1)
{
    __shared__ float As[TM*APAD];
    __shared__ float Ws[KC*Hv];
    int tid = threadIdx.x;
    int rg = tid >> 4, cg = tid & 15;
    int r0 = rg * 8, c0 = cg * 8;
    int row0 = blockIdx.x * TM;
    const float* Wc = W1 + 128 * Hv;   // agg chunk rows

    ull acc[8][4];
    #pragma unroll
    for (int r = 0; r < 8; r++)
        #pragma unroll
        for (int c = 0; c < 4; c++) acc[r][c] = 0ull;

    for (int k0 = 0; k0 < Hv; k0 += KC) {
        #pragma unroll
        for (int i = 0; i < 4; i++) {
            int lin = tid + i*128;
            int r = lin >> 3; int kk = (lin & 7) * 4;
            int row = row0 + r;
            float4 a = make_float4(0.f,0.f,0.f,0.f);
            if (row < BN) {
                int ir = irow_of(row);
                a = *(const float4*)&g_Agg[ir*Hv + k0 + kk];
                float s = g_segsum[ir];
                float inv = (s > 0.f) ? 1.f/s : 0.f;
                a.x *= inv; a.y *= inv; a.z *= inv; a.w *= inv;
            }
            *(float4*)&As[r*APAD + kk] = a;
        }
        load_w(Wc, k0, Ws, tid);
        __syncthreads();
        mm_chunk(As, Ws, r0, c0, acc);
        __syncthreads();
    }
    float4 bi0 = *(const float4*)&b1[c0];
    float4 bi1 = *(const float4*)&b1[c0 + 4];
    #pragma unroll
    for (int r = 0; r < 8; r++) {
        int row = row0 + r0 + r;
        if (row < BN) {
            float4 p0 = *(const float4*)&g_Hpart[row*Hv + c0];
            float4 p1 = *(const float4*)&g_Hpart[row*Hv + c0 + 4];
            float v[8];
            unpack2(acc[r][0], v[0], v[1]); unpack2(acc[r][1], v[2], v[3]);
            unpack2(acc[r][2], v[4], v[5]); unpack2(acc[r][3], v[6], v[7]);
            v[0]+=bi0.x+p0.x; v[1]+=bi0.y+p0.y; v[2]+=bi0.z+p0.z; v[3]+=bi0.w+p0.w;
            v[4]+=bi1.x+p1.x; v[5]+=bi1.y+p1.y; v[6]+=bi1.z+p1.z; v[7]+=bi1.w+p1.w;
            #pragma unroll
            for (int j = 0; j < 8; j++) v[j] = v[j] / (1.f + expf(-v[j]));
            *(float4*)&g_Hmid[row*Hv + c0]     = make_float4(v[0],v[1],v[2],v[3]);
            *(float4*)&g_Hmid[row*Hv + c0 + 4] = make_float4(v[4],v[5],v[6],v[7]);
        }
    }
}

// ---------------- 5: GEMM2 + residual + LayerNorm ----------------
__global__ void __launch_bounds__(128)
gemm2_ln(const float* __restrict__ hidden,
         const float* __restrict__ W2, const float* __restrict__ b2,
         const float* __restrict__ gamma, const float* __restrict__ beta,
         float* __restrict__ out)
{
    __shared__ float As[TM*APAD];
    __shared__ float Ws[KC*Hv];
    int tid = threadIdx.x;
    int rg = tid >> 4, cg = tid & 15;
    int r0 = rg * 8, c0 = cg * 8;
    int row0 = blockIdx.x * TM;

    ull acc[8][4];
    #pragma unroll
    for (int r = 0; r < 8; r++)
        #pragma unroll
        for (int c = 0; c < 4; c++) acc[r][c] = 0ull;

    for (int k0 = 0; k0 < Hv; k0 += KC) {
        #pragma unroll
        for (int i = 0; i < 4; i++) {
            int lin = tid + i*128;
            int r = lin >> 3; int kk = (lin & 7) * 4;
            int row = row0 + r;
            float4 a = make_float4(0.f,0.f,0.f,0.f);
            if (row < BN) a = *(const float4*)&g_Hmid[row*Hv + k0 + kk];
            *(float4*)&As[r*APAD + kk] = a;
        }
        load_w(W2, k0, Ws, tid);
        __syncthreads();
        mm_chunk(As, Ws, r0, c0, acc);
        __syncthreads();
    }

    float4 b20 = *(const float4*)&b2[c0];
    float4 b21 = *(const float4*)&b2[c0 + 4];
    float4 gv0 = *(const float4*)&gamma[c0];
    float4 gv1 = *(const float4*)&gamma[c0 + 4];
    float4 be0 = *(const float4*)&beta[c0];
    float4 be1 = *(const float4*)&beta[c0 + 4];

    #pragma unroll
    for (int r = 0; r < 8; r++) {
        int row = row0 + r0 + r;
        float x[8];
        if (row < BN) {
            float4 h0 = *(const float4*)&hidden[row*Hv + c0];
            float4 h1 = *(const float4*)&hidden[row*Hv + c0 + 4];
            float v[8];
            unpack2(acc[r][0], v[0], v[1]); unpack2(acc[r][1], v[2], v[3]);
            unpack2(acc[r][2], v[4], v[5]); unpack2(acc[r][3], v[6], v[7]);
            x[0] = v[0]+b20.x+h0.x; x[1] = v[1]+b20.y+h0.y;
            x[2] = v[2]+b20.z+h0.z; x[3] = v[3]+b20.w+h0.w;
            x[4] = v[4]+b21.x+h1.x; x[5] = v[5]+b21.y+h1.y;
            x[6] = v[6]+b21.z+h1.z; x[7] = v[7]+b21.w+h1.w;
        } else {
            #pragma unroll
            for (int j = 0; j < 8; j++) x[j] = 0.f;
        }
        float s = 0.f, ss = 0.f;
        #pragma unroll
        for (int j = 0; j < 8; j++) { s += x[j]; ss += x[j]*x[j]; }
        #pragma unroll
        for (int off = 8; off > 0; off >>= 1) {
            s  += __shfl_xor_sync(0xffffffffu, s, off);
            ss += __shfl_xor_sync(0xffffffffu, ss, off);
        }
        if (row < BN) {
            float mean = s * (1.f/128.f);
            float var  = ss * (1.f/128.f) - mean*mean;
            float rstd = rsqrtf(var + EPSv);
            float4 o0, o1;
            o0.x = (x[0]-mean)*rstd*gv0.x + be0.x;
            o0.y = (x[1]-mean)*rstd*gv0.y + be0.y;
            o0.z = (x[2]-mean)*rstd*gv0.z + be0.z;
            o0.w = (x[3]-mean)*rstd*gv0.w + be0.w;
            o1.x = (x[4]-mean)*rstd*gv1.x + be1.x;
            o1.y = (x[5]-mean)*rstd*gv1.y + be1.y;
            o1.z = (x[6]-mean)*rstd*gv1.z + be1.z;
            o1.w = (x[7]-mean)*rstd*gv1.w + be1.w;
            *(float4*)&out[row*Hv + c0]     = o0;
            *(float4*)&out[row*Hv + c0 + 4] = o1;
        }
    }
}

// ---------------- launch (two-stream fork/join, capture-safe) ----------------
extern "C" void kernel_launch(void* const* d_in, const int* in_sizes, int n_in,
                              void* d_out, int out_size)
{
    const float* hidden = (const float*)d_in[0];
    const float* temb   = (const float*)d_in[1];
    const int*   eidx   = (const int*)d_in[2];
    const int*   etype  = (const int*)d_in[3];
    const float* eemb   = (const float*)d_in[4];
    const float* Wq = (const float*)d_in[5];  const float* bq = (const float*)d_in[6];
    const float* Wk = (const float*)d_in[7];  const float* bk = (const float*)d_in[8];
    const float* Wv = (const float*)d_in[9];  const float* bv = (const float*)d_in[10];
    const float* We = (const float*)d_in[11]; const float* be = (const float*)d_in[12];
    const float* W1 = (const float*)d_in[13]; const float* b1 = (const float*)d_in[14];
    const float* W2 = (const float*)d_in[15]; const float* b2 = (const float*)d_in[16];
    const float* gamma = (const float*)d_in[17]; const float* beta = (const float*)d_in[18];
    float* out = (float*)d_out;

    int gb = (BN + TM - 1)/TM;   // 313

    cudaStream_t s1;
    cudaStreamCreateWithFlags(&s1, cudaStreamNonBlocking);
    cudaEvent_t eFork, ePrep, eQkv, eHt;
    cudaEventCreateWithFlags(&eFork, cudaEventDisableTiming);
    cudaEventCreateWithFlags(&ePrep, cudaEventDisableTiming);
    cudaEventCreateWithFlags(&eQkv,  cudaEventDisableTiming);
    cudaEventCreateWithFlags(&eHt,   cudaEventDisableTiming);

    // fork s1 off the main (capture) stream
    cudaEventRecord(eFork, 0);
    cudaStreamWaitEvent(s1, eFork, 0);

    // s1: zero + edge-type prep (concurrent with QKV GEMM below)
    zero_init<<<2560, 256, 0, s1>>>();
    prep_edge<<<1, 1024, 0, s1>>>(eemb, Wk, Wv, We, be);
    cudaEventRecord(ePrep, s1);

    // main: QKV GEMM
    dim3 gq(gb, 1, 3);
    gemm_qkv<<<gq, 128>>>(hidden, temb, Wq, bq, Wk, bk, Wv, bv);
    cudaEventRecord(eQkv, 0);

    // s1: mlp1 hidden+temb partial (concurrent with edge_fused)
    cudaStreamWaitEvent(s1, eQkv, 0);
    gemm_mlp1_ht<<<gb, 128, 0, s1>>>(hidden, temb, W1);
    cudaEventRecord(eHt, s1);

    // main: edge phase (needs zero_init + prep_edge complete)
    cudaStreamWaitEvent(0, ePrep, 0);
    edge_fused<<<Ev/8, 256>>>(eidx, etype);

    // join: mlp1 agg-chunk combine, then output GEMM
    cudaStreamWaitEvent(0, eHt, 0);
    gemm_mlp1_agg<<<gb, 128>>>(W1, b1);
    gemm2_ln<<<gb, 128>>>(hidden, W2, b2, gamma, beta, out);

    cudaEventDestroy(eFork);
    cudaEventDestroy(ePrep);
    cudaEventDestroy(eQkv);
    cudaEventDestroy(eHt);
    cudaStreamDestroy(s1);
}